// round 1
// baseline (speedup 1.0000x reference)
#include <cuda_runtime.h>
#include <cuda_bf16.h>

#define FULLMASK 0xFFFFFFFFu

// ---------------- problem constants ----------------
namespace {
constexpr int CELLS0 = 16 * 80 * 80;   // 102400
constexpr int CELLS1 = 16 * 40 * 40;   // 25600
constexpr int CELLS2 = 16 * 20 * 20;   // 6400
constexpr int TOTCELLS = CELLS0 + CELLS1 + CELLS2;  // 134400
constexpr int NTARGETS = 2048;
constexpr int NSLOT = 64;   // atomic contention spreading
}

// ---------------- static device scratch (no allocations) ----------------
__device__ int      g_win[TOTCELLS];          // winner target index per cell (-1 = empty)
__device__ unsigned g_cmask[TOTCELLS * 3];    // 96-bit class mask per cell
__device__ double   g_part[3 * 4 * NSLOT];    // [scale][metric][slot]; metric: 0=obj 1=box 2=cls 3=cnt

// ---------------- helpers ----------------
__device__ __forceinline__ float bce(float x, float t) {
    // max(x,0) - x*t + log1p(exp(-|x|))
    return fmaxf(x, 0.f) - x * t + log1pf(expf(-fabsf(x)));
}

// ---------------- kernel 1: reset scratch ----------------
__global__ void k_init() {
    int i = blockIdx.x * blockDim.x + threadIdx.x;
    int stride = gridDim.x * blockDim.x;
    for (; i < TOTCELLS * 3; i += stride) {
        g_cmask[i] = 0u;
        if (i < TOTCELLS) g_win[i] = -1;
        if (i < 3 * 4 * NSLOT) g_part[i] = 0.0;
    }
}

// ---------------- kernel 2: scatter targets into grids ----------------
__global__ void k_scatter(const float* __restrict__ tg) {
    int tid = blockIdx.x * blockDim.x + threadIdx.x;
    if (tid >= 3 * NTARGETS) return;
    int s = tid / NTARGETS;
    int j = tid - s * NTARGETS;
    const float* t = tg + j * 6;
    int b = (int)t[0];
    int c = (int)t[1];
    float bx = fminf(fmaxf(t[2], 0.f), 1.f);
    float by = fminf(fmaxf(t[3], 0.f), 1.f);
    int H, W, base;
    if (s == 0)      { H = 80; W = 80; base = 0; }
    else if (s == 1) { H = 40; W = 40; base = CELLS0; }
    else             { H = 20; W = 20; base = CELLS0 + CELLS1; }
    int gx = min(max((int)(bx * (float)W), 0), W - 1);
    int gy = min(max((int)(by * (float)H), 0), H - 1);
    int cell = base + (b * H + gy) * W + gx;
    // last-write-wins (target order) == max target index
    atomicMax(&g_win[cell], j);
    // every colliding target contributes its own class bit
    atomicOr(&g_cmask[cell * 3 + (c >> 5)], 1u << (c & 31));
}

// ---------------- kernel 3: fused loss over all scales; one warp per cell ----------------
__global__ void __launch_bounds__(256) k_main(const float* __restrict__ p0,
                                              const float* __restrict__ p1,
                                              const float* __restrict__ p2,
                                              const float* __restrict__ tg) {
    const int warpInBlock = threadIdx.x >> 5;
    const int lane = threadIdx.x & 31;
    const int gw = blockIdx.x * 8 + warpInBlock;   // global cell index (warp id)

    int s, cl, H, W;
    const float* pred;
    if (gw < CELLS0)            { s = 0; cl = gw;                   pred = p0; H = 80; W = 80; }
    else if (gw < CELLS0+CELLS1){ s = 1; cl = gw - CELLS0;          pred = p1; H = 40; W = 40; }
    else                        { s = 2; cl = gw - CELLS0 - CELLS1; pred = p2; H = 20; W = 20; }
    const int HW = H * W;
    const int b = cl / HW;
    const int rem = cl - b * HW;

    // anchor-0 row: 85 contiguous floats
    const float* row = pred + ((long)(b * 3) * HW + rem) * 85;
    float v0 = row[lane];
    float v1 = row[lane + 32];
    float v2 = (lane < 21) ? row[lane + 64] : 0.f;

    // uniform per-cell loads (same addr across warp -> single sector)
    int winner = g_win[gw];
    bool m = (winner >= 0);
    unsigned m0 = 0u, m1 = 0u, m2 = 0u;
    if (m) {
        m0 = g_cmask[gw * 3 + 0];
        m1 = g_cmask[gw * 3 + 1];
        m2 = g_cmask[gw * 3 + 2];
    }

    // ---- objectness: a=0 channel 4 (lane 4) + a=1, a=2 channel 4 (lanes 25/26)
    float objp = 0.f;
    if (lane == 4)  objp = bce(v0, m ? 1.f : 0.f);
    if (lane == 25) { float o = pred[((long)(b * 3 + 1) * HW + rem) * 85 + 4]; objp += bce(o, 0.f); }
    if (lane == 26) { float o = pred[((long)(b * 3 + 2) * HW + rem) * 85 + 4]; objp += bce(o, 0.f); }

    // ---- classification (only masked cells contribute)
    float clsp = 0.f;
    if (m) {
        if (lane >= 5) {                       // c = lane,     k = lane-5 in [0,26] -> word0
            int k = lane - 5;
            clsp += bce(v0, (float)((m0 >> k) & 1u));
        }
        {                                      // c = lane+32,  k = lane+27 in [27,58]
            int k = lane + 27;
            unsigned w_ = (k < 32) ? m0 : m1;
            clsp += bce(v1, (float)((w_ >> (k & 31)) & 1u));
        }
        if (lane < 21) {                       // c = lane+64,  k = lane+59 in [59,79]
            int k = lane + 59;
            unsigned w_ = (k < 64) ? m1 : m2;
            clsp += bce(v2, (float)((w_ >> (k & 31)) & 1u));
        }
    }

    // ---- box CIoU (lane 0 only; raw logits per reference)
    float px = __shfl_sync(FULLMASK, v0, 0);
    float py = __shfl_sync(FULLMASK, v0, 1);
    float pw = __shfl_sync(FULLMASK, v0, 2);
    float ph = __shfl_sync(FULLMASK, v0, 3);
    float boxp = 0.f;
    float cntp = 0.f;
    if (lane == 0 && m) {
        const float* t = tg + winner * 6;
        float tx = fminf(fmaxf(t[2], 0.f), 1.f);
        float ty = fminf(fmaxf(t[3], 0.f), 1.f);
        float tw = fminf(fmaxf(t[4], 0.f), 1.f);
        float th = fminf(fmaxf(t[5], 0.f), 1.f);

        float px1 = px - pw * 0.5f, py1 = py - ph * 0.5f;
        float px2 = px + pw * 0.5f, py2 = py + ph * 0.5f;
        float tx1 = tx - tw * 0.5f, ty1 = ty - th * 0.5f;
        float tx2 = tx + tw * 0.5f, ty2 = ty + th * 0.5f;

        float iw = fmaxf(fminf(px2, tx2) - fmaxf(px1, tx1), 0.f);
        float ih = fmaxf(fminf(py2, ty2) - fmaxf(py1, ty1), 0.f);
        float inter = iw * ih;
        float uni = pw * ph + tw * th - inter;
        float iou = inter / (uni + 1e-7f);

        float dx = px - tx, dy = py - ty;
        float cd = dx * dx + dy * dy;
        float ew = fmaxf(px2, tx2) - fminf(px1, tx1);
        float eh = fmaxf(py2, ty2) - fminf(py1, ty1);
        float ed = ew * ew + eh * eh + 1e-7f;

        float dv = atanf(tw / th) - atanf(pw / ph);
        float v = 0.4052847345693511f * dv * dv;   // 4/pi^2
        float alpha = v / (1.f - iou + v + 1e-7f);
        boxp = iou - cd / ed - alpha * v;
        cntp = 1.f;
    }

    // ---- warp reduce four partials
    for (int off = 16; off; off >>= 1) {
        objp += __shfl_down_sync(FULLMASK, objp, off);
        boxp += __shfl_down_sync(FULLMASK, boxp, off);
        clsp += __shfl_down_sync(FULLMASK, clsp, off);
        cntp += __shfl_down_sync(FULLMASK, cntp, off);
    }

    __shared__ float sh[8][4];
    if (lane == 0) {
        sh[warpInBlock][0] = objp;
        sh[warpInBlock][1] = boxp;
        sh[warpInBlock][2] = clsp;
        sh[warpInBlock][3] = cntp;
    }
    __syncthreads();
    // block is always fully inside one scale (12800/3200/800 block boundaries)
    if (threadIdx.x < 4) {
        float acc = 0.f;
        #pragma unroll
        for (int i = 0; i < 8; i++) acc += sh[i][threadIdx.x];
        int slot = blockIdx.x & (NSLOT - 1);
        atomicAdd(&g_part[(s * 4 + threadIdx.x) * NSLOT + slot], (double)acc);
    }
}

// ---------------- kernel 4: finalize ----------------
__global__ void k_final(float* __restrict__ out) {
    __shared__ double sums[12];
    int t = threadIdx.x;
    if (t < 12) {
        double a = 0.0;
        #pragma unroll
        for (int k = 0; k < NSLOT; k++) a += g_part[t * NSLOT + k];
        sums[t] = a;
    }
    __syncthreads();
    if (t == 0) {
        const double denom[3] = {16.0 * 3 * 80 * 80, 16.0 * 3 * 40 * 40, 16.0 * 3 * 20 * 20};
        double tb = 0.0, to = 0.0, tc = 0.0;
        for (int s = 0; s < 3; s++) {
            double obj = sums[s * 4 + 0];
            double box = sums[s * 4 + 1];
            double cls = sums[s * 4 + 2];
            double cnt = sums[s * 4 + 3];
            double n = fmax(cnt, 1.0);
            tb += 1.0 - box / n;
            to += obj / denom[s];
            tc += cls / (n * 80.0);
        }
        double tot = 7.5 * tb + 1.0 * to + 0.5 * tc;
        out[0] = (float)tot;
        out[1] = (float)tb;
        out[2] = (float)to;
        out[3] = (float)tc;
    }
}

// ---------------- launch ----------------
extern "C" void kernel_launch(void* const* d_in, const int* in_sizes, int n_in,
                              void* d_out, int out_size) {
    const float* p0 = (const float*)d_in[0];
    const float* p1 = (const float*)d_in[1];
    const float* p2 = (const float*)d_in[2];
    const float* tg = (const float*)d_in[3];
    float* out = (float*)d_out;

    k_init<<<(TOTCELLS * 3 + 255) / 256, 256>>>();
    k_scatter<<<(3 * NTARGETS + 255) / 256, 256>>>(tg);
    k_main<<<TOTCELLS / 8, 256>>>(p0, p1, p2, tg);
    k_final<<<1, 32>>>(out);
}

// round 3
// speedup vs baseline: 3.9594x; 3.9594x over previous
#include <cuda_runtime.h>
#include <cuda_bf16.h>

#define FULLMASK 0xFFFFFFFFu

// ---------------- problem constants ----------------
namespace {
constexpr int CELLS0 = 16 * 80 * 80;   // 102400 (cells, scale 0)
constexpr int CELLS1 = 16 * 40 * 40;   // 25600
constexpr int CELLS2 = 16 * 20 * 20;   // 6400
constexpr int TOTCELLS = CELLS0 + CELLS1 + CELLS2;      // 134400
constexpr int OBJ0 = CELLS0 * 3;       // 307200 obj logits scale 0 (all anchors)
constexpr int OBJ1 = CELLS1 * 3;       // 76800
constexpr int OBJ2 = CELLS2 * 3;       // 19200
constexpr int OBJTOT = OBJ0 + OBJ1 + OBJ2;              // 403200
constexpr int NTARGETS = 2048;
constexpr int NSLOT = 64;
constexpr int SCATTER_BLOCKS = 24;     // 24*256 = 6144 = 3*2048 scatter threads
constexpr int OBJ_BLOCKS = OBJTOT / 256;                // 1575
constexpr int SPARSE_BLOCKS = (3 * NTARGETS) / 8;       // 768 blocks, 8 warps each
}

// ---------------- static device scratch (zero-initialized; self-cleaning) ----
__device__ int      g_win[TOTCELLS];         // winner+1 per cell (0 = empty)
__device__ unsigned g_cmask[TOTCELLS * 3];   // 96-bit class mask per cell
__device__ double   g_part[3 * 4 * NSLOT];   // [scale][metric][slot] 0=obj 1=box 2=cls 3=cnt

__device__ __forceinline__ float softplus_(float x) {   // bce(x, 0)
    return fmaxf(x, 0.f) + log1pf(expf(-fabsf(x)));
}
__device__ __forceinline__ float bce(float x, float t) {
    return fmaxf(x, 0.f) - x * t + log1pf(expf(-fabsf(x)));
}

// ============ kernel A: scatter targets (blocks 0..23) + dense obj softplus ===
__global__ void __launch_bounds__(256) k_phase1(const float* __restrict__ p0,
                                                const float* __restrict__ p1,
                                                const float* __restrict__ p2,
                                                const float* __restrict__ tg) {
    if (blockIdx.x < SCATTER_BLOCKS) {
        int tid = blockIdx.x * 256 + threadIdx.x;       // [0, 6144)
        int s = tid / NTARGETS;
        int j = tid - s * NTARGETS;
        const float* t = tg + j * 6;
        int b = (int)t[0];
        int c = (int)t[1];
        float bx = fminf(fmaxf(t[2], 0.f), 1.f);
        float by = fminf(fmaxf(t[3], 0.f), 1.f);
        int H, W, base;
        if (s == 0)      { H = 80; W = 80; base = 0; }
        else if (s == 1) { H = 40; W = 40; base = CELLS0; }
        else             { H = 20; W = 20; base = CELLS0 + CELLS1; }
        int gx = min(max((int)(bx * (float)W), 0), W - 1);
        int gy = min(max((int)(by * (float)H), 0), H - 1);
        int cell = base + (b * H + gy) * W + gx;
        atomicMax(&g_win[cell], j + 1);                 // last-write-wins == max j
        atomicOr(&g_cmask[cell * 3 + (c >> 5)], 1u << (c & 31));
        return;
    }

    // ---- dense objectness: sum softplus over ALL (scale, b, a, h, w) logits
    int bi = blockIdx.x - SCATTER_BLOCKS;               // [0, 1575)
    int i = bi * 256 + threadIdx.x;                     // obj element index
    int s, idx;
    const float* pred;
    if (i < OBJ0)             { s = 0; idx = i;               pred = p0; }
    else if (i < OBJ0 + OBJ1) { s = 1; idx = i - OBJ0;        pred = p1; }
    else                      { s = 2; idx = i - OBJ0 - OBJ1; pred = p2; }
    float x = __ldg(pred + (long)idx * 85 + 4);
    float v = softplus_(x);

    // block reduce
    for (int off = 16; off; off >>= 1) v += __shfl_down_sync(FULLMASK, v, off);
    __shared__ float sh[8];
    int lane = threadIdx.x & 31, w = threadIdx.x >> 5;
    if (lane == 0) sh[w] = v;
    __syncthreads();
    if (threadIdx.x == 0) {
        float acc = 0.f;
        #pragma unroll
        for (int k = 0; k < 8; k++) acc += sh[k];
        atomicAdd(&g_part[(s * 4 + 0) * NSLOT + (blockIdx.x & (NSLOT - 1))], (double)acc);
    }
}

// ============ kernel B: sparse box/cls/obj-correction; warp per (scale,target);
//              self-cleans g_win / g_cmask for the next graph replay. ==========
__global__ void __launch_bounds__(256) k_sparse(const float* __restrict__ p0,
                                                const float* __restrict__ p1,
                                                const float* __restrict__ p2,
                                                const float* __restrict__ tg) {
    const int lane = threadIdx.x & 31;
    const int gw = blockIdx.x * 8 + (threadIdx.x >> 5); // [0, 6144)
    const int s = gw / NTARGETS;
    const int j = gw - s * NTARGETS;

    const float* t = tg + j * 6;
    int b = (int)t[0];
    float bx = fminf(fmaxf(t[2], 0.f), 1.f);
    float by = fminf(fmaxf(t[3], 0.f), 1.f);
    int H, W, base;
    const float* pred;
    if (s == 0)      { H = 80; W = 80; base = 0;               pred = p0; }
    else if (s == 1) { H = 40; W = 40; base = CELLS0;          pred = p1; }
    else             { H = 20; W = 20; base = CELLS0 + CELLS1; pred = p2; }
    int gx = min(max((int)(bx * (float)W), 0), W - 1);
    int gy = min(max((int)(by * (float)H), 0), H - 1);
    int cell = base + (b * H + gy) * W + gx;

    if (g_win[cell] != j + 1) return;                   // not the winner

    // a=0 row of this cell
    int rem = gy * W + gx;
    const float* row = pred + ((long)(b * 3) * (H * W) + rem) * 85;
    float v0 = row[lane];
    float v1 = row[lane + 32];
    float v2 = (lane < 21) ? row[lane + 64] : 0.f;

    unsigned m0 = g_cmask[cell * 3 + 0];
    unsigned m1 = g_cmask[cell * 3 + 1];
    unsigned m2 = g_cmask[cell * 3 + 2];

    // self-clean for next replay (winner warp is unique per cell; non-winners
    // returned on the compare above, and 0 != j+1 for any j, so a racing
    // non-winner that reads 0 still returns correctly)
    if (lane == 0) {
        g_win[cell] = 0;
        g_cmask[cell * 3 + 0] = 0u;
        g_cmask[cell * 3 + 1] = 0u;
        g_cmask[cell * 3 + 2] = 0u;
    }

    // ---- classification over channels 5..84
    float clsp = 0.f;
    if (lane >= 5) {                 // c = lane      -> bit lane-5  (word 0)
        clsp += bce(v0, (float)((m0 >> (lane - 5)) & 1u));
    }
    {                                // c = lane+32   -> bit lane+27
        int k = lane + 27;
        unsigned wd = (k < 32) ? m0 : m1;
        clsp += bce(v1, (float)((wd >> (k & 31)) & 1u));
    }
    if (lane < 21) {                 // c = lane+64   -> bit lane+59
        int k = lane + 59;
        unsigned wd = (k < 64) ? m1 : m2;
        clsp += bce(v2, (float)((wd >> (k & 31)) & 1u));
    }

    // ---- obj correction: bce(x,1) - bce(x,0) = -x at this cell's a=0 obj logit
    float objp = (lane == 4) ? -v0 : 0.f;

    // ---- box CIoU on lane 0
    float px = __shfl_sync(FULLMASK, v0, 0);
    float py = __shfl_sync(FULLMASK, v0, 1);
    float pw = __shfl_sync(FULLMASK, v0, 2);
    float ph = __shfl_sync(FULLMASK, v0, 3);
    float boxp = 0.f, cntp = 0.f;
    if (lane == 0) {
        float tx = bx, ty = by;
        float tw = fminf(fmaxf(t[4], 0.f), 1.f);
        float th = fminf(fmaxf(t[5], 0.f), 1.f);
        float px1 = px - pw * 0.5f, py1 = py - ph * 0.5f;
        float px2 = px + pw * 0.5f, py2 = py + ph * 0.5f;
        float tx1 = tx - tw * 0.5f, ty1 = ty - th * 0.5f;
        float tx2 = tx + tw * 0.5f, ty2 = ty + th * 0.5f;
        float iw = fmaxf(fminf(px2, tx2) - fmaxf(px1, tx1), 0.f);
        float ih = fmaxf(fminf(py2, ty2) - fmaxf(py1, ty1), 0.f);
        float inter = iw * ih;
        float uni = pw * ph + tw * th - inter;
        float iou = inter / (uni + 1e-7f);
        float dx = px - tx, dy = py - ty;
        float cd = dx * dx + dy * dy;
        float ew = fmaxf(px2, tx2) - fminf(px1, tx1);
        float eh = fmaxf(py2, ty2) - fminf(py1, ty1);
        float ed = ew * ew + eh * eh + 1e-7f;
        float dv = atanf(tw / th) - atanf(pw / ph);
        float v = 0.4052847345693511f * dv * dv;        // 4/pi^2
        float alpha = v / (1.f - iou + v + 1e-7f);
        boxp = iou - cd / ed - alpha * v;
        cntp = 1.f;
    }

    // ---- warp reduce, then 4 double atomics
    for (int off = 16; off; off >>= 1) {
        objp += __shfl_down_sync(FULLMASK, objp, off);
        boxp += __shfl_down_sync(FULLMASK, boxp, off);
        clsp += __shfl_down_sync(FULLMASK, clsp, off);
        cntp += __shfl_down_sync(FULLMASK, cntp, off);
    }
    if (lane == 0) {
        int slot = gw & (NSLOT - 1);
        atomicAdd(&g_part[(s * 4 + 0) * NSLOT + slot], (double)objp);
        atomicAdd(&g_part[(s * 4 + 1) * NSLOT + slot], (double)boxp);
        atomicAdd(&g_part[(s * 4 + 2) * NSLOT + slot], (double)clsp);
        atomicAdd(&g_part[(s * 4 + 3) * NSLOT + slot], (double)cntp);
    }
}

// ============ kernel C: finalize; reads AND resets g_part ====================
__global__ void __launch_bounds__(768) k_final(float* __restrict__ out) {
    __shared__ double sh[12 * NSLOT];
    __shared__ double red[12];           // separate buffer: no read/write overlap
    int t = threadIdx.x;                 // 768 = 12 * 64
    double v = g_part[t];
    g_part[t] = 0.0;                     // reset for next graph replay
    sh[t] = v;
    __syncthreads();
    if (t < 12) {
        double a = 0.0;
        #pragma unroll
        for (int k = 0; k < NSLOT; k++) a += sh[t * NSLOT + k];
        red[t] = a;
    }
    __syncthreads();
    if (t == 0) {
        const double denom[3] = {16.0 * 3 * 80 * 80, 16.0 * 3 * 40 * 40, 16.0 * 3 * 20 * 20};
        double tb = 0.0, to = 0.0, tc = 0.0;
        for (int s = 0; s < 3; s++) {
            double obj = red[s * 4 + 0];
            double box = red[s * 4 + 1];
            double cls = red[s * 4 + 2];
            double cnt = red[s * 4 + 3];
            double n = fmax(cnt, 1.0);
            tb += 1.0 - box / n;
            to += obj / denom[s];
            tc += cls / (n * 80.0);
        }
        double tot = 7.5 * tb + 1.0 * to + 0.5 * tc;
        out[0] = (float)tot;
        out[1] = (float)tb;
        out[2] = (float)to;
        out[3] = (float)tc;
    }
}

// ---------------- launch ----------------
extern "C" void kernel_launch(void* const* d_in, const int* in_sizes, int n_in,
                              void* d_out, int out_size) {
    const float* p0 = (const float*)d_in[0];
    const float* p1 = (const float*)d_in[1];
    const float* p2 = (const float*)d_in[2];
    const float* tg = (const float*)d_in[3];
    float* out = (float*)d_out;

    k_phase1<<<SCATTER_BLOCKS + OBJ_BLOCKS, 256>>>(p0, p1, p2, tg);
    k_sparse<<<SPARSE_BLOCKS, 256>>>(p0, p1, p2, tg);   // 768 blocks * 8 warps = 6144
    k_final<<<1, 768>>>(out);
}